// round 7
// baseline (speedup 1.0000x reference)
#include <cuda_runtime.h>
#include <cuda_fp16.h>
#include <cstdint>
#include <math.h>

#define BB 4
#define SS 2048
#define DD 1024
#define LOSCALE 2048.0f
#define INVLOSCALE 4.8828125e-4f

// ---------------------------------------------------------------------------
// Scratch (device globals — allocation-free per harness rules)
// fp16 operand buffers use [hi | lo] layout: row length = 2*Kphys.
// lo is pre-scaled by 2048 (corrections accumulate scaled; epilogue rescales).
// ---------------------------------------------------------------------------
__device__ __half g_x3 [(size_t)BB * SS * 2 * DD];   // x split      [8192][2048]
__device__ __half g_wqt[(size_t)DD * 2 * DD];        // Wq^T split   [1024][2048]
__device__ __half g_wkt[(size_t)DD * 2 * DD];
__device__ __half g_wvt[(size_t)DD * 2 * DD];
__device__ __half g_q3 [(size_t)BB * SS * 2 * DD];   // q split
__device__ __half g_k3 [(size_t)BB * SS * 2 * DD];   // k split
__device__ float  g_vf [(size_t)BB * SS * DD];       // v fp32
__device__ __half g_vt3[(size_t)BB * DD * 2 * SS];   // v^T split  [b][1024][4096]
__device__ float  g_s  [(size_t)BB * SS * SS];       // raw scores fp32
__device__ __half g_a3 [(size_t)BB * SS * 2 * SS];   // attn split [b][2048][4096]

// ---------------------------------------------------------------------------
// PTX helpers (compute_103-safe: cp.async, ldmatrix, mma.sync only)
// ---------------------------------------------------------------------------
__device__ __forceinline__ void cp16(uint32_t dst, const void* src) {
    asm volatile("cp.async.cg.shared.global [%0], [%1], 16;\n" :: "r"(dst), "l"(src));
}
__device__ __forceinline__ uint32_t swz128(uint32_t off) { return off ^ ((off >> 3) & 0x70); }

__device__ __forceinline__ void ldsm4(uint32_t& r0, uint32_t& r1, uint32_t& r2, uint32_t& r3,
                                      uint32_t addr) {
    asm volatile("ldmatrix.sync.aligned.m8n8.x4.shared.b16 {%0,%1,%2,%3}, [%4];"
                 : "=r"(r0), "=r"(r1), "=r"(r2), "=r"(r3) : "r"(addr));
}

// fp32-accumulate fp16 MMA (main pass)
__device__ __forceinline__ void mma_f32a(float c[4], const uint32_t a[4], const uint32_t b0,
                                         const uint32_t b1) {
    asm volatile(
        "mma.sync.aligned.m16n8k16.row.col.f32.f16.f16.f32 "
        "{%0,%1,%2,%3}, {%4,%5,%6,%7}, {%8,%9}, {%0,%1,%2,%3};\n"
        : "+f"(c[0]), "+f"(c[1]), "+f"(c[2]), "+f"(c[3])
        : "r"(a[0]), "r"(a[1]), "r"(a[2]), "r"(a[3]), "r"(b0), "r"(b1));
}

// fp16-accumulate fp16 MMA (correction passes; 2x rate on Hopper-lineage pipes)
__device__ __forceinline__ void mma_f16a(uint32_t c[2], const uint32_t a[4], const uint32_t b0,
                                         const uint32_t b1) {
    asm volatile(
        "mma.sync.aligned.m16n8k16.row.col.f16.f16.f16.f16 "
        "{%0,%1}, {%2,%3,%4,%5}, {%6,%7}, {%0,%1};\n"
        : "+r"(c[0]), "+r"(c[1])
        : "r"(a[0]), "r"(a[1]), "r"(a[2]), "r"(a[3]), "r"(b0), "r"(b1));
}

// ---------------------------------------------------------------------------
// mma.sync GEMM, flat 1-D grid, tile decode by sched. CTA tile 128x128, BK=64,
// 3-stage cp.async, 128 threads = 4 warps of 64x64, ldmatrix.x4 fragments with
// register double-buffering.
// fp32 = hi + 2^-11*lo' realized as 3 K-passes:
//   pass 0: Al'*Bh (f16 acc)   A offset P, B offset 0
//   pass 1: Ah*Bl' (f16 acc)   A offset 0, B offset P
//   pass 2: Ah*Bh  (f32 acc, seeded with 2^-11 * f16 acc)
// sched 1: fused QKV (w = t>>9 selects Wq/Wk/Wv; q/k epilogue emits split fp16)
// sched 2: scores QK^T, triangular causal tile list (136 tiles per batch)
// sched 3: attn @ V, K clamped at diagonal block, longest tiles first
// ---------------------------------------------------------------------------
#define NSTAGE 3
#define STAGE_BYTES 32768            // A 16KB + B 16KB
#define GEMM_SMEM (NSTAGE * STAGE_BYTES)

__global__ __launch_bounds__(128, 2)
void gemm_mma(int sched,
              const __half* __restrict__ A,
              const __half* __restrict__ B0,
              const __half* __restrict__ B1,
              const __half* __restrict__ B2,
              void* __restrict__ C0, void* __restrict__ C1, void* __restrict__ C2)
{
    extern __shared__ __align__(1024) char smem[];
    const uint32_t base0 = (uint32_t)__cvta_generic_to_shared(smem);

    const int tid  = threadIdx.x;
    const int wid  = tid >> 5;
    const int lane = tid & 31;
    const int wm   = wid >> 1;      // 0..1
    const int wn   = wid & 1;       // 0..1

    // ---- decode tile ----
    const int t = blockIdx.x;
    const __half *Ag, *Bg;
    void* Cv;
    int m0, n0, N_C, rowL, nCk, mode, P;
    if (sched == 1) {                       // fused QKV
        const int w = t >> 9;
        const int r = t & 511;
        m0 = (r >> 3) * 128; n0 = (r & 7) * 128;
        Ag = A;
        Bg = (w == 0) ? B0 : ((w == 1) ? B1 : B2);
        Cv = (w == 0) ? C0 : ((w == 1) ? C1 : C2);
        mode = (w == 2) ? 0 : 1;
        N_C = DD; rowL = 2 * DD; nCk = DD / 64; P = DD;
    } else if (sched == 2) {                // scores, triangular decode
        const int z  = t / 136;
        const int tt = t - z * 136;
        int r = (int)floorf((sqrtf(8.0f * tt + 1.0f) - 1.0f) * 0.5f);
        while ((r + 1) * (r + 2) / 2 <= tt) r++;
        while (r * (r + 1) / 2 > tt) r--;
        const int c = tt - r * (r + 1) / 2;
        m0 = r * 128; n0 = c * 128;
        Ag = A  + (size_t)z * SS * 2 * DD;
        Bg = B0 + (size_t)z * SS * 2 * DD;
        Cv = (float*)C0 + (size_t)z * SS * SS;
        mode = 0; N_C = SS; rowL = 2 * DD; nCk = DD / 64; P = DD;
    } else {                                // attn @ V, longest-first
        const int m    = 15 - (t >> 5);
        const int rest = t & 31;
        m0 = m * 128; n0 = (rest & 7) * 128;
        const int z = rest >> 3;
        Ag = A  + (size_t)z * SS * 2 * SS;
        Bg = B0 + (size_t)z * DD * 2 * SS;
        Cv = (float*)C0 + (size_t)z * SS * DD;
        mode = 0; N_C = DD; rowL = 2 * SS;
        nCk = min(SS / 64, 2 * m + 2); P = SS;
    }
    const int nC = 3 * nCk;
    const int nCorr = 2 * nCk;              // correction chunks (f16 acc)

    // ldmatrix fragment offsets within a stage (rows of 128B, SW128 swizzle)
    const int mo  = ((lane >> 3) & 1) * 8 + (lane & 7);
    const int akb = ((lane >> 4) & 1) * 16;
    const int no  = ((lane >> 4) & 1) * 8 + (lane & 7);
    const int bkb = ((lane >> 3) & 1) * 16;
    uint32_t aoff[4][4], boff[4][4];
    #pragma unroll
    for (int ks = 0; ks < 4; ks++)
        #pragma unroll
        for (int f = 0; f < 4; f++) {
            aoff[ks][f] = swz128((uint32_t)((wm * 64 + f * 16 + mo) * 128 + ks * 32 + akb));
            boff[ks][f] = swz128((uint32_t)((wn * 64 + f * 16 + no) * 128 + ks * 32 + bkb));
        }

    float acc[4][8][4];
    uint32_t acch[4][8][2];
    #pragma unroll
    for (int i = 0; i < 4; i++)
        #pragma unroll
        for (int j = 0; j < 8; j++) { acch[i][j][0] = 0u; acch[i][j][1] = 0u; }

    // chunk loader: thread loads A row m0+tid and B row n0+tid (128B each)
    auto load_chunk = [&](int c) {
        const int st = c % NSTAGE;
        const int p  = c / nCk;
        const int ip = c - p * nCk;
        const int pA = (p == 0) ? P : 0;
        const int pB = (p == 1) ? P : 0;
        const uint32_t aBase = base0 + st * STAGE_BYTES;
        const uint32_t bBase = aBase + 16384;
        const __half* as = Ag + (size_t)(m0 + tid) * rowL + pA + ip * 64;
        const __half* bs = Bg + (size_t)(n0 + tid) * rowL + pB + ip * 64;
        const uint32_t ro = (uint32_t)tid * 128;
        #pragma unroll
        for (int s8 = 0; s8 < 8; s8++) {
            cp16(aBase + swz128(ro + s8 * 16), as + s8 * 8);
            cp16(bBase + swz128(ro + s8 * 16), bs + s8 * 8);
        }
        asm volatile("cp.async.commit_group;\n");
    };

    load_chunk(0);
    if (nC > 1) load_chunk(1);

    uint32_t af[2][4][4], bf[2][4][4];

    for (int c = 0; c < nC; ++c) {
        if (c + 1 < nC) asm volatile("cp.async.wait_group 1;\n" ::: "memory");
        else            asm volatile("cp.async.wait_group 0;\n" ::: "memory");
        __syncthreads();

        if (c + 2 < nC) load_chunk(c + 2);

        // phase boundary: seed f32 acc with scaled f16 correction sums
        if (c == nCorr) {
            #pragma unroll
            for (int im = 0; im < 4; im++)
                #pragma unroll
                for (int jn = 0; jn < 8; jn++) {
                    const __half2 d0 = *reinterpret_cast<const __half2*>(&acch[im][jn][0]);
                    const __half2 d1 = *reinterpret_cast<const __half2*>(&acch[im][jn][1]);
                    acc[im][jn][0] = __low2float(d0)  * INVLOSCALE;
                    acc[im][jn][1] = __high2float(d0) * INVLOSCALE;
                    acc[im][jn][2] = __low2float(d1)  * INVLOSCALE;
                    acc[im][jn][3] = __high2float(d1) * INVLOSCALE;
                }
        }

        const uint32_t aB = base0 + (c % NSTAGE) * STAGE_BYTES;
        const uint32_t bB = aB + 16384;

        // prime ks=0 fragments
        #pragma unroll
        for (int f = 0; f < 4; f++)
            ldsm4(af[0][f][0], af[0][f][1], af[0][f][2], af[0][f][3], aB + aoff[0][f]);
        #pragma unroll
        for (int f = 0; f < 4; f++)
            ldsm4(bf[0][f][0], bf[0][f][1], bf[0][f][2], bf[0][f][3], bB + boff[0][f]);

        if (c < nCorr) {
            #pragma unroll
            for (int ks = 0; ks < 4; ks++) {
                const int p = ks & 1;
                if (ks < 3) {
                    const int q = 1 - p;
                    #pragma unroll
                    for (int f = 0; f < 4; f++)
                        ldsm4(af[q][f][0], af[q][f][1], af[q][f][2], af[q][f][3],
                              aB + aoff[ks + 1][f]);
                    #pragma unroll
                    for (int f = 0; f < 4; f++)
                        ldsm4(bf[q][f][0], bf[q][f][1], bf[q][f][2], bf[q][f][3],
                              bB + boff[ks + 1][f]);
                }
                #pragma unroll
                for (int im = 0; im < 4; im++)
                    #pragma unroll
                    for (int jn = 0; jn < 8; jn++)
                        mma_f16a(acch[im][jn], af[p][im],
                                 bf[p][jn >> 1][(jn & 1) * 2], bf[p][jn >> 1][(jn & 1) * 2 + 1]);
            }
        } else {
            #pragma unroll
            for (int ks = 0; ks < 4; ks++) {
                const int p = ks & 1;
                if (ks < 3) {
                    const int q = 1 - p;
                    #pragma unroll
                    for (int f = 0; f < 4; f++)
                        ldsm4(af[q][f][0], af[q][f][1], af[q][f][2], af[q][f][3],
                              aB + aoff[ks + 1][f]);
                    #pragma unroll
                    for (int f = 0; f < 4; f++)
                        ldsm4(bf[q][f][0], bf[q][f][1], bf[q][f][2], bf[q][f][3],
                              bB + boff[ks + 1][f]);
                }
                #pragma unroll
                for (int im = 0; im < 4; im++)
                    #pragma unroll
                    for (int jn = 0; jn < 8; jn++)
                        mma_f32a(acc[im][jn], af[p][im],
                                 bf[p][jn >> 1][(jn & 1) * 2], bf[p][jn >> 1][(jn & 1) * 2 + 1]);
            }
        }
    }

    // ---- epilogue ----
    #pragma unroll
    for (int im = 0; im < 4; im++) {
        const int r = m0 + wm * 64 + im * 16 + (lane >> 2);
        #pragma unroll
        for (int jn = 0; jn < 8; jn++) {
            const int cc = n0 + wn * 64 + jn * 8 + (lane & 3) * 2;
            if (mode == 0) {
                float* Cg = (float*)Cv;
                *(float2*)(Cg + (size_t)r * N_C + cc)       = make_float2(acc[im][jn][0], acc[im][jn][1]);
                *(float2*)(Cg + (size_t)(r + 8) * N_C + cc) = make_float2(acc[im][jn][2], acc[im][jn][3]);
            } else {
                __half* Cg = (__half*)Cv;
                #pragma unroll
                for (int hr = 0; hr < 2; hr++) {
                    const float v0 = acc[im][jn][hr * 2];
                    const float v1 = acc[im][jn][hr * 2 + 1];
                    const __half h0 = __float2half(v0);
                    const __half l0 = __float2half((v0 - __half2float(h0)) * LOSCALE);
                    const __half h1 = __float2half(v1);
                    const __half l1 = __float2half((v1 - __half2float(h1)) * LOSCALE);
                    __half* row = Cg + (size_t)(r + hr * 8) * (2 * N_C);
                    *(__half2*)(row + cc)       = __halves2half2(h0, h1);
                    *(__half2*)(row + N_C + cc) = __halves2half2(l0, l1);
                }
            }
        }
    }
}

// ---------------------------------------------------------------------------
// fp32 -> [hi | lo*2048] fp16 split, same row layout (row len 2K).
// ---------------------------------------------------------------------------
__global__ __launch_bounds__(256)
void conv_split2(const float* __restrict__ src, __half* __restrict__ dst, int K)
{
    const long long idx = (long long)blockIdx.x * 256 + threadIdx.x;
    const long long m = idx / K;
    const int j = (int)(idx % K);
    const float v = src[idx];
    const __half h = __float2half(v);
    const __half l = __float2half((v - __half2float(h)) * LOSCALE);
    __half* o = dst + m * 2LL * K;
    o[j] = h; o[K + j] = l;
}

// ---------------------------------------------------------------------------
// Merged weight transpose: fp32 [D][D] -> split fp16 [D][2D], 3 weights via z.
// ---------------------------------------------------------------------------
__global__ __launch_bounds__(256)
void transposeW(const float* __restrict__ s0, const float* __restrict__ s1,
                const float* __restrict__ s2,
                __half* __restrict__ d0, __half* __restrict__ d1,
                __half* __restrict__ d2)
{
    __shared__ float tile[32][33];
    const int z = blockIdx.z;
    const float* src = (z == 0) ? s0 : ((z == 1) ? s1 : s2);
    __half*      dst = (z == 0) ? d0 : ((z == 1) ? d1 : d2);
    const int r0 = blockIdx.y * 32, c0 = blockIdx.x * 32;
    const int tx = threadIdx.x & 31;
    const int ty = threadIdx.x >> 5;

    #pragma unroll
    for (int dy = 0; dy < 32; dy += 8)
        tile[ty + dy][tx] = src[(size_t)(r0 + ty + dy) * DD + c0 + tx];
    __syncthreads();

    #pragma unroll
    for (int dy = 0; dy < 32; dy += 8) {
        const int c = c0 + ty + dy;
        const int r = r0 + tx;
        const float v = tile[tx][ty + dy];
        const __half h = __float2half(v);
        const __half l = __float2half((v - __half2float(h)) * LOSCALE);
        __half* o = dst + (size_t)c * 2 * DD;
        o[r] = h; o[DD + r] = l;
    }
}

// ---------------------------------------------------------------------------
// v transpose: fp32 [S][D] per batch -> split fp16 [D][2S]
// ---------------------------------------------------------------------------
__global__ __launch_bounds__(256)
void transposeV(const float* __restrict__ src, __half* __restrict__ dst)
{
    __shared__ float tile[32][33];
    src += (size_t)blockIdx.z * SS * DD;
    dst += (size_t)blockIdx.z * DD * 2 * SS;
    const int r0 = blockIdx.y * 32, c0 = blockIdx.x * 32;
    const int tx = threadIdx.x & 31;
    const int ty = threadIdx.x >> 5;

    #pragma unroll
    for (int dy = 0; dy < 32; dy += 8)
        tile[ty + dy][tx] = src[(size_t)(r0 + ty + dy) * DD + c0 + tx];
    __syncthreads();

    #pragma unroll
    for (int dy = 0; dy < 32; dy += 8) {
        const int c = c0 + ty + dy;
        const int r = r0 + tx;
        const float v = tile[tx][ty + dy];
        const __half h = __float2half(v);
        const __half l = __float2half((v - __half2float(h)) * LOSCALE);
        __half* o = dst + (size_t)c * 2 * SS;
        o[r] = h; o[SS + r] = l;
    }
}

// ---------------------------------------------------------------------------
// Causal softmax emitting split fp16 attn [hi | lo*2048]. Zero-fills only up
// to the 128-row diagonal-block boundary (AV K-clamp never reads past it).
// ---------------------------------------------------------------------------
__global__ __launch_bounds__(256)
void softmax2(const float* __restrict__ Sc, __half* __restrict__ A3,
              int S, float scale)
{
    const long long row = blockIdx.x;            // b*S + i
    const int i = (int)(row % S);
    const float* p = Sc + row * (long long)S;
    __half* out = A3 + row * (long long)(2 * S);
    const int L = i + 1;
    const int Lz = ((i >> 7) + 1) << 7;          // diagonal-block end

    const int tid  = threadIdx.x;
    const int lane = tid & 31;
    const int wid  = tid >> 5;
    __shared__ float red[32];

    float mx = -INFINITY;
    for (int j = tid; j < L; j += 256) mx = fmaxf(mx, p[j]);
    #pragma unroll
    for (int o = 16; o; o >>= 1) mx = fmaxf(mx, __shfl_xor_sync(0xffffffffu, mx, o));
    if (lane == 0) red[wid] = mx;
    __syncthreads();
    if (tid == 0) {
        float m = red[0];
        #pragma unroll
        for (int w = 1; w < 8; w++) m = fmaxf(m, red[w]);
        red[0] = m;
    }
    __syncthreads();
    mx = red[0];
    __syncthreads();

    float e[8];
    float sum = 0.0f;
    int cnt = 0;
    for (int j = tid; j < L; j += 256) {
        const float ev = __expf((p[j] - mx) * scale);
        e[cnt++] = ev;
        sum += ev;
    }
    #pragma unroll
    for (int o = 16; o; o >>= 1) sum += __shfl_xor_sync(0xffffffffu, sum, o);
    if (lane == 0) red[wid] = sum;
    __syncthreads();
    if (tid == 0) {
        float s = red[0];
        #pragma unroll
        for (int w = 1; w < 8; w++) s += red[w];
        red[0] = s;
    }
    __syncthreads();
    const float inv = 1.0f / red[0];

    cnt = 0;
    for (int j = tid; j < L; j += 256) {
        const float v = e[cnt++] * inv;
        const __half h = __float2half(v);
        const __half l = __float2half((v - __half2float(h)) * LOSCALE);
        out[j] = h; out[S + j] = l;
    }
    const __half zero = __float2half(0.0f);
    for (int j = L + tid; j < Lz; j += 256) {
        out[j] = zero; out[S + j] = zero;
    }
}

// ---------------------------------------------------------------------------
extern "C" void kernel_launch(void* const* d_in, const int* in_sizes, int n_in,
                              void* d_out, int out_size)
{
    (void)in_sizes; (void)n_in; (void)out_size;
    const float* x  = (const float*)d_in[0];
    const float* Wq = (const float*)d_in[1];
    const float* Wk = (const float*)d_in[2];
    const float* Wv = (const float*)d_in[3];
    float* out = (float*)d_out;

    __half *x3, *wqt, *wkt, *wvt, *q3, *k3, *vt3, *a3;
    float *vf, *s;
    cudaGetSymbolAddress((void**)&x3,  g_x3);
    cudaGetSymbolAddress((void**)&wqt, g_wqt);
    cudaGetSymbolAddress((void**)&wkt, g_wkt);
    cudaGetSymbolAddress((void**)&wvt, g_wvt);
    cudaGetSymbolAddress((void**)&q3,  g_q3);
    cudaGetSymbolAddress((void**)&k3,  g_k3);
    cudaGetSymbolAddress((void**)&vf,  g_vf);
    cudaGetSymbolAddress((void**)&vt3, g_vt3);
    cudaGetSymbolAddress((void**)&s,   g_s);
    cudaGetSymbolAddress((void**)&a3,  g_a3);

    cudaFuncSetAttribute(gemm_mma, cudaFuncAttributeMaxDynamicSharedMemorySize, GEMM_SMEM);

    const int B = BB, S = SS, D = DD;
    const long long MS = (long long)B * S;   // 8192

    // launch 0: x conversion
    conv_split2<<<(int)(MS * D / 256), 256>>>(x, x3, D);

    // launch 1: merged weight transposes
    {
        dim3 tg(D / 32, D / 32, 3);
        transposeW<<<tg, 256>>>(Wq, Wk, Wv, wqt, wkt, wvt);
    }

    // launch 2: fused QKV projections (1536 tiles)
    gemm_mma<<<1536, 128, GEMM_SMEM>>>(1, x3, wqt, wkt, wvt, q3, k3, vf);

    // launch 3 (ncu-captured): scores = Q K^T, triangular tile list
    gemm_mma<<<136 * B, 128, GEMM_SMEM>>>(2, q3, k3, nullptr, nullptr,
                                          s, nullptr, nullptr);

    // launch 4: v transpose-split
    {
        dim3 tg(D / 32, S / 32, B);
        transposeV<<<tg, 256>>>(vf, vt3);
    }

    // launch 5: softmax -> split fp16 attn
    softmax2<<<B * S, 256>>>(s, a3, S, 0.03125f);

    // launch 6: out = attn @ V (K-clamped, longest tiles first)
    gemm_mma<<<16 * 8 * B, 128, GEMM_SMEM>>>(3, a3, vt3, nullptr, nullptr,
                                             out, nullptr, nullptr);
}

// round 8
// speedup vs baseline: 1.3029x; 1.3029x over previous
#include <cuda_runtime.h>
#include <cuda_bf16.h>
#include <cstdint>
#include <math.h>

#define BB 4
#define SS 2048
#define DD 1024

// ---------------------------------------------------------------------------
// Scratch (device globals — allocation-free per harness rules)
// bf16 operand buffers use [hi | lo] row layout: row length = 2*Kphys.
// lo is UNSCALED (bf16 exponent range = fp32, no subnormal risk), so all three
// split products accumulate directly into one fp32 accumulator.
// ---------------------------------------------------------------------------
__device__ __nv_bfloat16 g_x3 [(size_t)BB * SS * 2 * DD];   // x split      [8192][2048]
__device__ __nv_bfloat16 g_wqt[(size_t)DD * 2 * DD];        // Wq^T split   [1024][2048]
__device__ __nv_bfloat16 g_wkt[(size_t)DD * 2 * DD];
__device__ __nv_bfloat16 g_wvt[(size_t)DD * 2 * DD];
__device__ __nv_bfloat16 g_q3 [(size_t)BB * SS * 2 * DD];   // q split
__device__ __nv_bfloat16 g_k3 [(size_t)BB * SS * 2 * DD];   // k split
__device__ float         g_vf [(size_t)BB * SS * DD];       // v fp32
__device__ __nv_bfloat16 g_vt3[(size_t)BB * DD * 2 * SS];   // v^T split  [b][1024][4096]
__device__ float         g_s  [(size_t)BB * SS * SS];       // raw scores fp32
__device__ __nv_bfloat16 g_a3 [(size_t)BB * SS * 2 * SS];   // attn split [b][2048][4096]

// ---------------------------------------------------------------------------
// PTX helpers (compute_103-safe: cp.async, ldmatrix, mma.sync only)
// ---------------------------------------------------------------------------
__device__ __forceinline__ void cp16(uint32_t dst, const void* src) {
    asm volatile("cp.async.cg.shared.global [%0], [%1], 16;\n" :: "r"(dst), "l"(src));
}
__device__ __forceinline__ uint32_t swz128(uint32_t off) { return off ^ ((off >> 3) & 0x70); }

__device__ __forceinline__ void ldsm4(uint32_t& r0, uint32_t& r1, uint32_t& r2, uint32_t& r3,
                                      uint32_t addr) {
    asm volatile("ldmatrix.sync.aligned.m8n8.x4.shared.b16 {%0,%1,%2,%3}, [%4];"
                 : "=r"(r0), "=r"(r1), "=r"(r2), "=r"(r3) : "r"(addr));
}

__device__ __forceinline__ void mma_bf16(float c[4], const uint32_t a[4], const uint32_t b0,
                                         const uint32_t b1) {
    asm volatile(
        "mma.sync.aligned.m16n8k16.row.col.f32.bf16.bf16.f32 "
        "{%0,%1,%2,%3}, {%4,%5,%6,%7}, {%8,%9}, {%0,%1,%2,%3};\n"
        : "+f"(c[0]), "+f"(c[1]), "+f"(c[2]), "+f"(c[3])
        : "r"(a[0]), "r"(a[1]), "r"(a[2]), "r"(a[3]), "r"(b0), "r"(b1));
}

// ---------------------------------------------------------------------------
// Fused-pass mma.sync GEMM. CTA tile 128x128, logical BK=32 per chunk.
// Each 128B SMEM row packs [hi 64B | lo 64B] of the SAME 32 k-columns, so a
// single chunk load serves all three split products:
//   acc += Ah*Bh + Ah*Bl + Al*Bh        (Al*Bl dropped, ~2^-16 relative)
// k16 slot map within a row: slot0/1 = hi k0-15/k16-31, slot2/3 = lo.
// 3-stage cp.async, 128 threads = 4 warps of 64x64, ldmatrix.x4 fragments.
// sched 1: fused QKV (w = t>>9 selects Wq/Wk/Wv; q/k epilogue emits split bf16)
// sched 2: scores QK^T, triangular causal tile list (136 tiles per batch)
// sched 3: attn @ V, K clamped at diagonal block, longest tiles first
// ---------------------------------------------------------------------------
#define NSTAGE 3
#define STAGE_BYTES 32768            // A 16KB + B 16KB
#define GEMM_SMEM (NSTAGE * STAGE_BYTES)

__global__ __launch_bounds__(128, 2)
void gemm_mma(int sched,
              const __nv_bfloat16* __restrict__ A,
              const __nv_bfloat16* __restrict__ B0,
              const __nv_bfloat16* __restrict__ B1,
              const __nv_bfloat16* __restrict__ B2,
              void* __restrict__ C0, void* __restrict__ C1, void* __restrict__ C2)
{
    extern __shared__ __align__(1024) char smem[];
    const uint32_t base0 = (uint32_t)__cvta_generic_to_shared(smem);

    const int tid  = threadIdx.x;
    const int wid  = tid >> 5;
    const int lane = tid & 31;
    const int wm   = wid >> 1;      // 0..1
    const int wn   = wid & 1;       // 0..1

    // ---- decode tile ----
    const int t = blockIdx.x;
    const __nv_bfloat16 *Ag, *Bg;
    void* Cv;
    int m0, n0, N_C, rowL, nC, mode, P;
    if (sched == 1) {                       // fused QKV
        const int w = t >> 9;
        const int r = t & 511;
        m0 = (r >> 3) * 128; n0 = (r & 7) * 128;
        Ag = A;
        Bg = (w == 0) ? B0 : ((w == 1) ? B1 : B2);
        Cv = (w == 0) ? C0 : ((w == 1) ? C1 : C2);
        mode = (w == 2) ? 0 : 1;
        N_C = DD; rowL = 2 * DD; nC = DD / 32; P = DD;
    } else if (sched == 2) {                // scores, triangular decode
        const int z  = t / 136;
        const int tt = t - z * 136;
        int r = (int)floorf((sqrtf(8.0f * tt + 1.0f) - 1.0f) * 0.5f);
        while ((r + 1) * (r + 2) / 2 <= tt) r++;
        while (r * (r + 1) / 2 > tt) r--;
        const int c = tt - r * (r + 1) / 2;
        m0 = r * 128; n0 = c * 128;
        Ag = A  + (size_t)z * SS * 2 * DD;
        Bg = B0 + (size_t)z * SS * 2 * DD;
        Cv = (float*)C0 + (size_t)z * SS * SS;
        mode = 0; N_C = SS; rowL = 2 * DD; nC = DD / 32; P = DD;
    } else {                                // attn @ V, longest-first
        const int m    = 15 - (t >> 5);
        const int rest = t & 31;
        m0 = m * 128; n0 = (rest & 7) * 128;
        const int z = rest >> 3;
        Ag = A  + (size_t)z * SS * 2 * SS;
        Bg = B0 + (size_t)z * DD * 2 * SS;
        Cv = (float*)C0 + (size_t)z * SS * DD;
        mode = 0; N_C = DD; rowL = 2 * SS;
        nC = min(SS / 32, 4 * m + 4); P = SS;
    }

    // ldmatrix fragment offsets within a stage (rows of 128B, SW128 swizzle)
    // slots 0..3: hi k0-15, hi k16-31, lo k0-15, lo k16-31
    const int mo  = ((lane >> 3) & 1) * 8 + (lane & 7);
    const int akb = ((lane >> 4) & 1) * 16;
    const int no  = ((lane >> 4) & 1) * 8 + (lane & 7);
    const int bkb = ((lane >> 3) & 1) * 16;
    uint32_t aoff[4][4], boff[4][4];
    #pragma unroll
    for (int ks = 0; ks < 4; ks++)
        #pragma unroll
        for (int f = 0; f < 4; f++) {
            aoff[ks][f] = swz128((uint32_t)((wm * 64 + f * 16 + mo) * 128 + ks * 32 + akb));
            boff[ks][f] = swz128((uint32_t)((wn * 64 + f * 16 + no) * 128 + ks * 32 + bkb));
        }

    float acc[4][8][4];
    #pragma unroll
    for (int i = 0; i < 4; i++)
        #pragma unroll
        for (int j = 0; j < 8; j++)
            #pragma unroll
            for (int q = 0; q < 4; q++) acc[i][j][q] = 0.0f;

    // chunk loader: thread loads A row m0+tid and B row n0+tid.
    // Row = [hi 64B | lo 64B] of the same 32 k-columns.
    auto load_chunk = [&](int c) {
        const int st = c % NSTAGE;
        const uint32_t aBase = base0 + st * STAGE_BYTES;
        const uint32_t bBase = aBase + 16384;
        const __nv_bfloat16* ah = Ag + (size_t)(m0 + tid) * rowL + c * 32;
        const __nv_bfloat16* bh = Bg + (size_t)(n0 + tid) * rowL + c * 32;
        const uint32_t ro = (uint32_t)tid * 128;
        #pragma unroll
        for (int s4 = 0; s4 < 4; s4++) {
            cp16(aBase + swz128(ro + s4 * 16),      ah + s4 * 8);
            cp16(aBase + swz128(ro + 64 + s4 * 16), ah + P + s4 * 8);
            cp16(bBase + swz128(ro + s4 * 16),      bh + s4 * 8);
            cp16(bBase + swz128(ro + 64 + s4 * 16), bh + P + s4 * 8);
        }
        asm volatile("cp.async.commit_group;\n");
    };

    load_chunk(0);
    if (nC > 1) load_chunk(1);

    for (int c = 0; c < nC; ++c) {
        if (c + 1 < nC) asm volatile("cp.async.wait_group 1;\n" ::: "memory");
        else            asm volatile("cp.async.wait_group 0;\n" ::: "memory");
        __syncthreads();

        if (c + 2 < nC) load_chunk(c + 2);

        const uint32_t aB = base0 + (c % NSTAGE) * STAGE_BYTES;
        const uint32_t bB = aB + 16384;

        #pragma unroll
        for (int ks = 0; ks < 2; ks++) {
            uint32_t ah[4][4], al[4][4], bh[4][4], bl[4][4];
            #pragma unroll
            for (int f = 0; f < 4; f++)
                ldsm4(ah[f][0], ah[f][1], ah[f][2], ah[f][3], aB + aoff[ks][f]);
            #pragma unroll
            for (int f = 0; f < 4; f++)
                ldsm4(bh[f][0], bh[f][1], bh[f][2], bh[f][3], bB + boff[ks][f]);
            #pragma unroll
            for (int f = 0; f < 4; f++)
                ldsm4(al[f][0], al[f][1], al[f][2], al[f][3], aB + aoff[ks + 2][f]);
            #pragma unroll
            for (int f = 0; f < 4; f++)
                ldsm4(bl[f][0], bl[f][1], bl[f][2], bl[f][3], bB + boff[ks + 2][f]);

            // pass 1: Ah * Bh
            #pragma unroll
            for (int im = 0; im < 4; im++)
                #pragma unroll
                for (int jn = 0; jn < 8; jn++)
                    mma_bf16(acc[im][jn], ah[im],
                             bh[jn >> 1][(jn & 1) * 2], bh[jn >> 1][(jn & 1) * 2 + 1]);
            // pass 2: Ah * Bl
            #pragma unroll
            for (int im = 0; im < 4; im++)
                #pragma unroll
                for (int jn = 0; jn < 8; jn++)
                    mma_bf16(acc[im][jn], ah[im],
                             bl[jn >> 1][(jn & 1) * 2], bl[jn >> 1][(jn & 1) * 2 + 1]);
            // pass 3: Al * Bh
            #pragma unroll
            for (int im = 0; im < 4; im++)
                #pragma unroll
                for (int jn = 0; jn < 8; jn++)
                    mma_bf16(acc[im][jn], al[im],
                             bh[jn >> 1][(jn & 1) * 2], bh[jn >> 1][(jn & 1) * 2 + 1]);
        }
    }

    // ---- epilogue ----
    #pragma unroll
    for (int im = 0; im < 4; im++) {
        const int r = m0 + wm * 64 + im * 16 + (lane >> 2);
        #pragma unroll
        for (int jn = 0; jn < 8; jn++) {
            const int cc = n0 + wn * 64 + jn * 8 + (lane & 3) * 2;
            if (mode == 0) {
                float* Cg = (float*)Cv;
                *(float2*)(Cg + (size_t)r * N_C + cc)       = make_float2(acc[im][jn][0], acc[im][jn][1]);
                *(float2*)(Cg + (size_t)(r + 8) * N_C + cc) = make_float2(acc[im][jn][2], acc[im][jn][3]);
            } else {
                __nv_bfloat16* Cg = (__nv_bfloat16*)Cv;
                #pragma unroll
                for (int hr = 0; hr < 2; hr++) {
                    const float v0 = acc[im][jn][hr * 2];
                    const float v1 = acc[im][jn][hr * 2 + 1];
                    const __nv_bfloat16 h0 = __float2bfloat16(v0);
                    const __nv_bfloat16 l0 = __float2bfloat16(v0 - __bfloat162float(h0));
                    const __nv_bfloat16 h1 = __float2bfloat16(v1);
                    const __nv_bfloat16 l1 = __float2bfloat16(v1 - __bfloat162float(h1));
                    __nv_bfloat16* row = Cg + (size_t)(r + hr * 8) * (2 * N_C);
                    *(__nv_bfloat162*)(row + cc)       = __halves2bfloat162(h0, h1);
                    *(__nv_bfloat162*)(row + N_C + cc) = __halves2bfloat162(l0, l1);
                }
            }
        }
    }
}

// ---------------------------------------------------------------------------
// fp32 -> [hi | lo] bf16 split, same row layout (row len 2K).
// ---------------------------------------------------------------------------
__global__ __launch_bounds__(256)
void conv_split2(const float* __restrict__ src, __nv_bfloat16* __restrict__ dst, int K)
{
    const long long idx = (long long)blockIdx.x * 256 + threadIdx.x;
    const long long m = idx / K;
    const int j = (int)(idx % K);
    const float v = src[idx];
    const __nv_bfloat16 h = __float2bfloat16(v);
    const __nv_bfloat16 l = __float2bfloat16(v - __bfloat162float(h));
    __nv_bfloat16* o = dst + m * 2LL * K;
    o[j] = h; o[K + j] = l;
}

// ---------------------------------------------------------------------------
// Merged weight transpose: fp32 [D][D] -> split bf16 [D][2D], 3 weights via z.
// ---------------------------------------------------------------------------
__global__ __launch_bounds__(256)
void transposeW(const float* __restrict__ s0, const float* __restrict__ s1,
                const float* __restrict__ s2,
                __nv_bfloat16* __restrict__ d0, __nv_bfloat16* __restrict__ d1,
                __nv_bfloat16* __restrict__ d2)
{
    __shared__ float tile[32][33];
    const int z = blockIdx.z;
    const float* src = (z == 0) ? s0 : ((z == 1) ? s1 : s2);
    __nv_bfloat16* dst = (z == 0) ? d0 : ((z == 1) ? d1 : d2);
    const int r0 = blockIdx.y * 32, c0 = blockIdx.x * 32;
    const int tx = threadIdx.x & 31;
    const int ty = threadIdx.x >> 5;

    #pragma unroll
    for (int dy = 0; dy < 32; dy += 8)
        tile[ty + dy][tx] = src[(size_t)(r0 + ty + dy) * DD + c0 + tx];
    __syncthreads();

    #pragma unroll
    for (int dy = 0; dy < 32; dy += 8) {
        const int c = c0 + ty + dy;
        const int r = r0 + tx;
        const float v = tile[tx][ty + dy];
        const __nv_bfloat16 h = __float2bfloat16(v);
        const __nv_bfloat16 l = __float2bfloat16(v - __bfloat162float(h));
        __nv_bfloat16* o = dst + (size_t)c * 2 * DD;
        o[r] = h; o[DD + r] = l;
    }
}

// ---------------------------------------------------------------------------
// v transpose: fp32 [S][D] per batch -> split bf16 [D][2S]
// ---------------------------------------------------------------------------
__global__ __launch_bounds__(256)
void transposeV(const float* __restrict__ src, __nv_bfloat16* __restrict__ dst)
{
    __shared__ float tile[32][33];
    src += (size_t)blockIdx.z * SS * DD;
    dst += (size_t)blockIdx.z * DD * 2 * SS;
    const int r0 = blockIdx.y * 32, c0 = blockIdx.x * 32;
    const int tx = threadIdx.x & 31;
    const int ty = threadIdx.x >> 5;

    #pragma unroll
    for (int dy = 0; dy < 32; dy += 8)
        tile[ty + dy][tx] = src[(size_t)(r0 + ty + dy) * DD + c0 + tx];
    __syncthreads();

    #pragma unroll
    for (int dy = 0; dy < 32; dy += 8) {
        const int c = c0 + ty + dy;
        const int r = r0 + tx;
        const float v = tile[tx][ty + dy];
        const __nv_bfloat16 h = __float2bfloat16(v);
        const __nv_bfloat16 l = __float2bfloat16(v - __bfloat162float(h));
        __nv_bfloat16* o = dst + (size_t)c * 2 * SS;
        o[r] = h; o[SS + r] = l;
    }
}

// ---------------------------------------------------------------------------
// Causal softmax emitting split bf16 attn [hi | lo]. Zero-fills only up to the
// 128-row diagonal-block boundary (AV K-clamp never reads past it).
// ---------------------------------------------------------------------------
__global__ __launch_bounds__(256)
void softmax2(const float* __restrict__ Sc, __nv_bfloat16* __restrict__ A3,
              int S, float scale)
{
    const long long row = blockIdx.x;            // b*S + i
    const int i = (int)(row % S);
    const float* p = Sc + row * (long long)S;
    __nv_bfloat16* out = A3 + row * (long long)(2 * S);
    const int L = i + 1;
    const int Lz = ((i >> 7) + 1) << 7;          // diagonal-block end

    const int tid  = threadIdx.x;
    const int lane = tid & 31;
    const int wid  = tid >> 5;
    __shared__ float red[32];

    float mx = -INFINITY;
    for (int j = tid; j < L; j += 256) mx = fmaxf(mx, p[j]);
    #pragma unroll
    for (int o = 16; o; o >>= 1) mx = fmaxf(mx, __shfl_xor_sync(0xffffffffu, mx, o));
    if (lane == 0) red[wid] = mx;
    __syncthreads();
    if (tid == 0) {
        float m = red[0];
        #pragma unroll
        for (int w = 1; w < 8; w++) m = fmaxf(m, red[w]);
        red[0] = m;
    }
    __syncthreads();
    mx = red[0];
    __syncthreads();

    float e[8];
    float sum = 0.0f;
    int cnt = 0;
    for (int j = tid; j < L; j += 256) {
        const float ev = __expf((p[j] - mx) * scale);
        e[cnt++] = ev;
        sum += ev;
    }
    #pragma unroll
    for (int o = 16; o; o >>= 1) sum += __shfl_xor_sync(0xffffffffu, sum, o);
    if (lane == 0) red[wid] = sum;
    __syncthreads();
    if (tid == 0) {
        float s = red[0];
        #pragma unroll
        for (int w = 1; w < 8; w++) s += red[w];
        red[0] = s;
    }
    __syncthreads();
    const float inv = 1.0f / red[0];

    cnt = 0;
    for (int j = tid; j < L; j += 256) {
        const float v = e[cnt++] * inv;
        const __nv_bfloat16 h = __float2bfloat16(v);
        const __nv_bfloat16 l = __float2bfloat16(v - __bfloat162float(h));
        out[j] = h; out[S + j] = l;
    }
    const __nv_bfloat16 zero = __float2bfloat16(0.0f);
    for (int j = L + tid; j < Lz; j += 256) {
        out[j] = zero; out[S + j] = zero;
    }
}

// ---------------------------------------------------------------------------
extern "C" void kernel_launch(void* const* d_in, const int* in_sizes, int n_in,
                              void* d_out, int out_size)
{
    (void)in_sizes; (void)n_in; (void)out_size;
    const float* x  = (const float*)d_in[0];
    const float* Wq = (const float*)d_in[1];
    const float* Wk = (const float*)d_in[2];
    const float* Wv = (const float*)d_in[3];
    float* out = (float*)d_out;

    __nv_bfloat16 *x3, *wqt, *wkt, *wvt, *q3, *k3, *vt3, *a3;
    float *vf, *s;
    cudaGetSymbolAddress((void**)&x3,  g_x3);
    cudaGetSymbolAddress((void**)&wqt, g_wqt);
    cudaGetSymbolAddress((void**)&wkt, g_wkt);
    cudaGetSymbolAddress((void**)&wvt, g_wvt);
    cudaGetSymbolAddress((void**)&q3,  g_q3);
    cudaGetSymbolAddress((void**)&k3,  g_k3);
    cudaGetSymbolAddress((void**)&vf,  g_vf);
    cudaGetSymbolAddress((void**)&vt3, g_vt3);
    cudaGetSymbolAddress((void**)&s,   g_s);
    cudaGetSymbolAddress((void**)&a3,  g_a3);

    cudaFuncSetAttribute(gemm_mma, cudaFuncAttributeMaxDynamicSharedMemorySize, GEMM_SMEM);

    const int B = BB, S = SS, D = DD;
    const long long MS = (long long)B * S;   // 8192

    // launch 0: x conversion
    conv_split2<<<(int)(MS * D / 256), 256>>>(x, x3, D);

    // launch 1: merged weight transposes
    {
        dim3 tg(D / 32, D / 32, 3);
        transposeW<<<tg, 256>>>(Wq, Wk, Wv, wqt, wkt, wvt);
    }

    // launch 2: fused QKV projections (1536 tiles)
    gemm_mma<<<1536, 128, GEMM_SMEM>>>(1, x3, wqt, wkt, wvt, q3, k3, vf);

    // launch 3 (ncu-captured): scores = Q K^T, triangular tile list
    gemm_mma<<<136 * B, 128, GEMM_SMEM>>>(2, q3, k3, nullptr, nullptr,
                                          s, nullptr, nullptr);

    // launch 4: v transpose-split
    {
        dim3 tg(D / 32, S / 32, B);
        transposeV<<<tg, 256>>>(vf, vt3);
    }

    // launch 5: softmax -> split bf16 attn
    softmax2<<<B * S, 256>>>(s, a3, S, 0.03125f);

    // launch 6: out = attn @ V (K-clamped, longest tiles first)
    gemm_mma<<<16 * 8 * B, 128, GEMM_SMEM>>>(3, a3, vt3, nullptr, nullptr,
                                             out, nullptr, nullptr);
}